// round 1
// baseline (speedup 1.0000x reference)
#include <cuda_runtime.h>

#define D     128
#define EF    16
#define NMAX  50000

// Scratch (device globals; no allocation allowed)
__device__ float g_pool[NMAX * D];     // segment-sum accumulator (e2n / n2n)
__device__ float g_static[NMAX * D];   // static_message = e2n_pool @ W0
__device__ float g_A[NMAX * D];        // h @ W1
__device__ float g_Y[NMAX * D];        // h @ W2 (scattered through edges)
__device__ float g_h[NMAX * D];        // hidden state

__device__ __forceinline__ void red4(float* p, float4 v) {
    asm volatile("red.global.add.v4.f32 [%0], {%1,%2,%3,%4};"
                 :: "l"(p), "f"(v.x), "f"(v.y), "f"(v.z), "f"(v.w)
                 : "memory");
}

// ---------------------------------------------------------------------------
// Zero the pool accumulator
__global__ void k_zero(int n4) {
    int i = blockIdx.x * blockDim.x + threadIdx.x;
    int stride = gridDim.x * blockDim.x;
    float4 z = make_float4(0.f, 0.f, 0.f, 0.f);
    for (; i < n4; i += stride) ((float4*)g_pool)[i] = z;
}

// ---------------------------------------------------------------------------
// Per edge: relu(edge_feat[e] @ W_e2l)  -> atomic add into g_pool[e2n_dst[e]]
// One warp per edge. Lane owns 4 output columns.
__global__ void __launch_bounds__(256) k_edge(
    const float* __restrict__ ef, const float* __restrict__ We,
    const int* __restrict__ dst, int E)
{
    __shared__ float sW[EF * D];   // 8 KB
    for (int i = threadIdx.x; i < EF * D; i += blockDim.x) sW[i] = We[i];
    __syncthreads();

    int lane = threadIdx.x & 31;
    int gw   = (blockIdx.x * blockDim.x + threadIdx.x) >> 5;
    int nw   = (gridDim.x * blockDim.x) >> 5;
    int col  = lane * 4;

    for (int e = gw; e < E; e += nw) {
        float f = (lane < EF) ? ef[(size_t)e * EF + lane] : 0.f;
        float4 acc = make_float4(0.f, 0.f, 0.f, 0.f);
#pragma unroll
        for (int k = 0; k < EF; k++) {
            float fk = __shfl_sync(0xffffffffu, f, k);
            float4 w = *(const float4*)(sW + k * D + col);
            acc.x = fmaf(fk, w.x, acc.x);
            acc.y = fmaf(fk, w.y, acc.y);
            acc.z = fmaf(fk, w.z, acc.z);
            acc.w = fmaf(fk, w.w, acc.w);
        }
        acc.x = fmaxf(acc.x, 0.f);
        acc.y = fmaxf(acc.y, 0.f);
        acc.z = fmaxf(acc.z, 0.f);
        acc.w = fmaxf(acc.w, 0.f);
        red4(g_pool + (size_t)dst[e] * D + col, acc);
    }
}

// ---------------------------------------------------------------------------
// g_static = g_pool @ W0 ; zero g_pool rows after reading (ready for spmm 1)
// 256 threads, 8 warps, 8 rows per warp, 64 rows per block iteration.
__global__ void __launch_bounds__(256) k_gemm_w0(
    const float* __restrict__ W, int n)
{
    extern __shared__ float sm[];
    float* sW    = sm;            // D*D
    float* stage = sm + D * D;    // 8 warps * 8 rows * D

    for (int i = threadIdx.x; i < D * D; i += blockDim.x) sW[i] = W[i];
    __syncthreads();

    int warp = threadIdx.x >> 5;
    int lane = threadIdx.x & 31;
    int col  = lane * 4;
    float* st = stage + warp * (8 * D);
    float4 z = make_float4(0.f, 0.f, 0.f, 0.f);

    for (int r0 = blockIdx.x * 64 + warp * 8; r0 < n; r0 += gridDim.x * 64) {
        int rmax = n - r0; if (rmax > 8) rmax = 8;
#pragma unroll
        for (int rr = 0; rr < 8; rr++) {
            if (rr < rmax) {
                float4 v = *(const float4*)(g_pool + (size_t)(r0 + rr) * D + col);
                *(float4*)(st + rr * D + col) = v;
            }
        }
        __syncwarp();

        float acc[8][4];
#pragma unroll
        for (int rr = 0; rr < 8; rr++)
            acc[rr][0] = acc[rr][1] = acc[rr][2] = acc[rr][3] = 0.f;

        for (int k = 0; k < D; k++) {
            float4 w = *(const float4*)(sW + k * D + col);
#pragma unroll
            for (int rr = 0; rr < 8; rr++) {
                float x = st[rr * D + k];
                acc[rr][0] = fmaf(x, w.x, acc[rr][0]);
                acc[rr][1] = fmaf(x, w.y, acc[rr][1]);
                acc[rr][2] = fmaf(x, w.z, acc[rr][2]);
                acc[rr][3] = fmaf(x, w.w, acc[rr][3]);
            }
        }
#pragma unroll
        for (int rr = 0; rr < 8; rr++) {
            if (rr < rmax) {
                float4 o = make_float4(acc[rr][0], acc[rr][1], acc[rr][2], acc[rr][3]);
                *(float4*)(g_static + (size_t)(r0 + rr) * D + col) = o;
                *(float4*)(g_pool   + (size_t)(r0 + rr) * D + col) = z;  // ready for spmm
            }
        }
        __syncwarp();
    }
}

// ---------------------------------------------------------------------------
// g_A = X @ W1 ; g_Y = X @ W2   where X = relu(g_static) (use_h=0) or g_h (use_h=1)
__global__ void __launch_bounds__(256) k_gemmAB(
    const float* __restrict__ W1, const float* __restrict__ W2,
    int n, int use_h)
{
    extern __shared__ float sm[];
    float* sW1   = sm;                // D*D
    float* sW2   = sm + D * D;        // D*D
    float* stage = sm + 2 * D * D;    // 8 * 8 * D

    for (int i = threadIdx.x; i < D * D; i += blockDim.x) {
        sW1[i] = W1[i];
        sW2[i] = W2[i];
    }
    __syncthreads();

    int warp = threadIdx.x >> 5;
    int lane = threadIdx.x & 31;
    int col  = lane * 4;
    float* st = stage + warp * (8 * D);
    const float* X = use_h ? g_h : g_static;

    for (int r0 = blockIdx.x * 64 + warp * 8; r0 < n; r0 += gridDim.x * 64) {
        int rmax = n - r0; if (rmax > 8) rmax = 8;
#pragma unroll
        for (int rr = 0; rr < 8; rr++) {
            if (rr < rmax) {
                float4 v = *(const float4*)(X + (size_t)(r0 + rr) * D + col);
                if (!use_h) {
                    v.x = fmaxf(v.x, 0.f); v.y = fmaxf(v.y, 0.f);
                    v.z = fmaxf(v.z, 0.f); v.w = fmaxf(v.w, 0.f);
                }
                *(float4*)(st + rr * D + col) = v;
            }
        }
        __syncwarp();

        float accA[8][4], accY[8][4];
#pragma unroll
        for (int rr = 0; rr < 8; rr++)
            for (int c = 0; c < 4; c++) { accA[rr][c] = 0.f; accY[rr][c] = 0.f; }

        for (int k = 0; k < D; k++) {
            float4 w1 = *(const float4*)(sW1 + k * D + col);
            float4 w2 = *(const float4*)(sW2 + k * D + col);
#pragma unroll
            for (int rr = 0; rr < 8; rr++) {
                float x = st[rr * D + k];
                accA[rr][0] = fmaf(x, w1.x, accA[rr][0]);
                accA[rr][1] = fmaf(x, w1.y, accA[rr][1]);
                accA[rr][2] = fmaf(x, w1.z, accA[rr][2]);
                accA[rr][3] = fmaf(x, w1.w, accA[rr][3]);
                accY[rr][0] = fmaf(x, w2.x, accY[rr][0]);
                accY[rr][1] = fmaf(x, w2.y, accY[rr][1]);
                accY[rr][2] = fmaf(x, w2.z, accY[rr][2]);
                accY[rr][3] = fmaf(x, w2.w, accY[rr][3]);
            }
        }
#pragma unroll
        for (int rr = 0; rr < 8; rr++) {
            if (rr < rmax) {
                float4 a = make_float4(accA[rr][0], accA[rr][1], accA[rr][2], accA[rr][3]);
                float4 y = make_float4(accY[rr][0], accY[rr][1], accY[rr][2], accY[rr][3]);
                *(float4*)(g_A + (size_t)(r0 + rr) * D + col) = a;
                *(float4*)(g_Y + (size_t)(r0 + rr) * D + col) = y;
            }
        }
        __syncwarp();
    }
}

// ---------------------------------------------------------------------------
// n2n spmm (post-GEMM form): g_pool[dst] += g_Y[src].  One warp per edge.
__global__ void __launch_bounds__(256) k_spmm(
    const int* __restrict__ src, const int* __restrict__ dst, int E)
{
    int lane = threadIdx.x & 31;
    int gw   = (blockIdx.x * blockDim.x + threadIdx.x) >> 5;
    int nw   = (gridDim.x * blockDim.x) >> 5;
    for (int e = gw; e < E; e += nw) {
        int s = src[e], d = dst[e];
        float4 v = ((const float4*)(g_Y + (size_t)s * D))[lane];
        red4(g_pool + (size_t)d * D + lane * 4, v);
    }
}

// ---------------------------------------------------------------------------
// h_out = relu(static + A + pool); optionally zero pool for next spmm.
// out == nullptr -> write g_h, else write out (final iteration -> d_out).
__global__ void __launch_bounds__(256) k_merge(
    float* __restrict__ out, int n4, int zero_pool)
{
    int i = blockIdx.x * blockDim.x + threadIdx.x;
    int stride = gridDim.x * blockDim.x;
    float* dstp = out ? out : g_h;
    float4 z = make_float4(0.f, 0.f, 0.f, 0.f);
    for (; i < n4; i += stride) {
        float4 s = ((const float4*)g_static)[i];
        float4 a = ((const float4*)g_A)[i];
        float4 p = ((const float4*)g_pool)[i];
        float4 o;
        o.x = fmaxf(s.x + a.x + p.x, 0.f);
        o.y = fmaxf(s.y + a.y + p.y, 0.f);
        o.z = fmaxf(s.z + a.z + p.z, 0.f);
        o.w = fmaxf(s.w + a.w + p.w, 0.f);
        ((float4*)dstp)[i] = o;
        if (zero_pool) ((float4*)g_pool)[i] = z;
    }
}

// ---------------------------------------------------------------------------
extern "C" void kernel_launch(void* const* d_in, const int* in_sizes, int n_in,
                              void* d_out, int out_size)
{
    const float* edge_feat = (const float*)d_in[0];
    const float* W_e2l     = (const float*)d_in[1];
    const float* W0        = (const float*)d_in[2];
    const float* W1s[3] = { (const float*)d_in[3], (const float*)d_in[5], (const float*)d_in[7] };
    const float* W2s[3] = { (const float*)d_in[4], (const float*)d_in[6], (const float*)d_in[8] };
    const int* e2n_dst  = (const int*)d_in[9];
    const int* edge_src = (const int*)d_in[10];
    const int* edge_dst = (const int*)d_in[11];

    int E  = in_sizes[9];
    int n  = out_size / D;
    int n4 = (n * D) / 4;

    const int smem_w0 = (D * D + 8 * 8 * D) * (int)sizeof(float);        // 80 KB
    const int smem_ab = (2 * D * D + 8 * 8 * D) * (int)sizeof(float);    // 144 KB
    cudaFuncSetAttribute(k_gemm_w0, cudaFuncAttributeMaxDynamicSharedMemorySize, smem_w0);
    cudaFuncSetAttribute(k_gemmAB,  cudaFuncAttributeMaxDynamicSharedMemorySize, smem_ab);

    int gemm_blocks = (n + 63) / 64;

    k_zero<<<1024, 256>>>(n4);
    k_edge<<<2048, 256>>>(edge_feat, W_e2l, e2n_dst, E);
    k_gemm_w0<<<gemm_blocks, 256, smem_w0>>>(W0, n);   // also zeros pool

    for (int it = 0; it < 3; it++) {
        k_gemmAB<<<gemm_blocks, 256, smem_ab>>>(W1s[it], W2s[it], n, it > 0 ? 1 : 0);
        k_spmm<<<2048, 256>>>(edge_src, edge_dst, E);
        k_merge<<<1024, 256>>>(it == 2 ? (float*)d_out : nullptr, n4, it == 2 ? 0 : 1);
    }
}

// round 4
// speedup vs baseline: 1.2669x; 1.2669x over previous
#include <cuda_runtime.h>

#define D      128
#define EF     16
#define NMAX   50000
#define EMAX   1600000
#define NCHUNK_MAX 256   // ceil(NMAX/256) = 196 <= 256

// ---------------- scratch (device globals; zero-init, no allocation) -------
__device__ float g_pool[NMAX * D];     // e2n pooled edge messages
__device__ float g_static[NMAX * D];   // e2n_pool @ W0
__device__ float g_A[NMAX * D];        // X @ W1
__device__ float g_Y[NMAX * D];        // X @ W2
__device__ float g_h[NMAX * D];        // hidden state

__device__ int g_cnt[2][NMAX];         // [0]=e2n_dst hist, [1]=edge_dst hist
__device__ int g_off[2][NMAX + 1];
__device__ int g_cur[2][NMAX];
__device__ int g_csum[2][NCHUNK_MAX];  // per-chunk sums
__device__ int g_coff[2][NCHUNK_MAX];  // per-chunk exclusive offsets
__device__ int g_permA[EMAX];          // edge ids grouped by e2n_dst
__device__ int g_permB[EMAX];          // edge_src values grouped by edge_dst

// ---------------- f32x2 packed math helpers --------------------------------
__device__ __forceinline__ unsigned long long pack2(float x) {
    unsigned int u = __float_as_uint(x);
    unsigned long long r;
    asm("mov.b64 %0, {%1, %2};" : "=l"(r) : "r"(u), "r"(u));
    return r;
}
__device__ __forceinline__ unsigned long long ffma2(
    unsigned long long a, unsigned long long b, unsigned long long c) {
    unsigned long long d;
    asm("fma.rn.f32x2 %0, %1, %2, %3;" : "=l"(d) : "l"(a), "l"(b), "l"(c));
    return d;
}
__device__ __forceinline__ float2 unpack2(unsigned long long v) {
    unsigned int lo, hi;
    asm("mov.b64 {%0, %1}, %2;" : "=r"(lo), "=r"(hi) : "l"(v));
    return make_float2(__uint_as_float(lo), __uint_as_float(hi));
}

// ---------------- CSR builders ---------------------------------------------
__global__ void k_zero_cnt(int n) {
    int i = blockIdx.x * blockDim.x + threadIdx.x;
    int s = gridDim.x * blockDim.x;
    for (; i < n; i += s) { g_cnt[0][i] = 0; g_cnt[1][i] = 0; }
}

__global__ void k_hist(const int* __restrict__ e2n, const int* __restrict__ ndst, int E) {
    int i = blockIdx.x * blockDim.x + threadIdx.x;
    int s = gridDim.x * blockDim.x;
    for (; i < E; i += s) {
        atomicAdd(&g_cnt[0][e2n[i]], 1);
        atomicAdd(&g_cnt[1][ndst[i]], 1);
    }
}

// Pass 1: per-chunk sums. grid = (nchunk, 2), block = 256.
__global__ void k_scan1(int n) {
    __shared__ int sh[256];
    int a = blockIdx.y;
    int i = blockIdx.x * 256 + threadIdx.x;
    sh[threadIdx.x] = (i < n) ? g_cnt[a][i] : 0;
    __syncthreads();
    for (int o = 128; o > 0; o >>= 1) {
        if (threadIdx.x < o) sh[threadIdx.x] += sh[threadIdx.x + o];
        __syncthreads();
    }
    if (threadIdx.x == 0) g_csum[a][blockIdx.x] = sh[0];
}

// Pass 2: single block, exclusive scan of chunk sums (nchunk <= 256).
__global__ void k_scan2(int n, int nchunk) {
    __shared__ int sh[256];
    for (int a = 0; a < 2; a++) {
        int v = (threadIdx.x < nchunk) ? g_csum[a][threadIdx.x] : 0;
        sh[threadIdx.x] = v;
        __syncthreads();
        for (int o = 1; o < 256; o <<= 1) {
            int t = (threadIdx.x >= o) ? sh[threadIdx.x - o] : 0;
            __syncthreads();
            sh[threadIdx.x] += t;
            __syncthreads();
        }
        if (threadIdx.x < nchunk) g_coff[a][threadIdx.x] = sh[threadIdx.x] - v;
        if (threadIdx.x == 255)   g_off[a][n] = sh[255];
        __syncthreads();
    }
}

// Pass 3: per-chunk local exclusive scan + chunk offset -> off, cur.
__global__ void k_scan3(int n) {
    __shared__ int sh[256];
    int a = blockIdx.y;
    int i = blockIdx.x * 256 + threadIdx.x;
    int v = (i < n) ? g_cnt[a][i] : 0;
    sh[threadIdx.x] = v;
    __syncthreads();
    for (int o = 1; o < 256; o <<= 1) {
        int t = (threadIdx.x >= o) ? sh[threadIdx.x - o] : 0;
        __syncthreads();
        sh[threadIdx.x] += t;
        __syncthreads();
    }
    if (i < n) {
        int excl = g_coff[a][blockIdx.x] + sh[threadIdx.x] - v;
        g_off[a][i] = excl;
        g_cur[a][i] = excl;
    }
}

__global__ void k_fill(const int* __restrict__ e2n, const int* __restrict__ ndst,
                       const int* __restrict__ nsrc, int E) {
    int i = blockIdx.x * blockDim.x + threadIdx.x;
    int s = gridDim.x * blockDim.x;
    for (; i < E; i += s) {
        int pa = atomicAdd(&g_cur[0][e2n[i]], 1);
        g_permA[pa] = i;
        int pb = atomicAdd(&g_cur[1][ndst[i]], 1);
        g_permB[pb] = nsrc[i];
    }
}

// ---------------------------------------------------------------------------
// Per-node e2n pool: g_pool[d] = sum over incoming edges of relu(ef[e] @ We).
// One warp per node; lane owns 4 output columns (f32x2 packed FMA).
__global__ void __launch_bounds__(256) k_edge_pool(
    const float* __restrict__ ef, const float* __restrict__ We, int n)
{
    __shared__ float sW[EF * D];   // 8 KB
    for (int i = threadIdx.x; i < EF * D; i += blockDim.x) sW[i] = We[i];
    __syncthreads();

    int lane = threadIdx.x & 31;
    int gw   = (blockIdx.x * blockDim.x + threadIdx.x) >> 5;
    int nw   = (gridDim.x * blockDim.x) >> 5;
    int col  = lane * 4;

    for (int d = gw; d < n; d += nw) {
        int j0 = g_off[0][d], j1 = g_off[0][d + 1];
        float a0 = 0.f, a1 = 0.f, a2 = 0.f, a3 = 0.f;
        for (int j = j0; j < j1; j++) {
            int e = g_permA[j];
            float f = (lane < EF) ? ef[(size_t)e * EF + lane] : 0.f;
            unsigned long long t0 = 0ull, t1 = 0ull;
#pragma unroll
            for (int k = 0; k < EF; k++) {
                float xk = __shfl_sync(0xffffffffu, f, k);
                unsigned long long xx = pack2(xk);
                ulonglong2 w = *(const ulonglong2*)(sW + k * D + col);
                t0 = ffma2(xx, w.x, t0);
                t1 = ffma2(xx, w.y, t1);
            }
            float2 p0 = unpack2(t0), p1 = unpack2(t1);
            a0 += fmaxf(p0.x, 0.f);
            a1 += fmaxf(p0.y, 0.f);
            a2 += fmaxf(p1.x, 0.f);
            a3 += fmaxf(p1.y, 0.f);
        }
        *(float4*)(g_pool + (size_t)d * D + col) = make_float4(a0, a1, a2, a3);
    }
}

// ---------------------------------------------------------------------------
// g_static = g_pool @ W0  (f32x2 packed). 8 rows/warp, 64 rows/block-iter.
__global__ void __launch_bounds__(256) k_gemm_w0(const float* __restrict__ W, int n)
{
    extern __shared__ float sm[];
    float* sW    = sm;            // D*D  (64 KB)
    float* stage = sm + D * D;    // 8*8*D (32 KB)

    for (int i = threadIdx.x; i < D * D; i += blockDim.x) sW[i] = W[i];
    __syncthreads();

    int warp = threadIdx.x >> 5;
    int lane = threadIdx.x & 31;
    int col  = lane * 4;
    float* st = stage + warp * (8 * D);

    for (int r0 = blockIdx.x * 64 + warp * 8; r0 < n; r0 += gridDim.x * 64) {
        int rmax = n - r0; if (rmax > 8) rmax = 8;
#pragma unroll
        for (int rr = 0; rr < 8; rr++)
            if (rr < rmax)
                *(float4*)(st + rr * D + col) =
                    *(const float4*)(g_pool + (size_t)(r0 + rr) * D + col);
        __syncwarp();

        unsigned long long a0[8], a1[8];
#pragma unroll
        for (int rr = 0; rr < 8; rr++) { a0[rr] = 0ull; a1[rr] = 0ull; }

        for (int k = 0; k < D; k++) {
            ulonglong2 w = *(const ulonglong2*)(sW + k * D + col);
#pragma unroll
            for (int rr = 0; rr < 8; rr++) {
                unsigned long long xx = pack2(st[rr * D + k]);
                a0[rr] = ffma2(xx, w.x, a0[rr]);
                a1[rr] = ffma2(xx, w.y, a1[rr]);
            }
        }
#pragma unroll
        for (int rr = 0; rr < 8; rr++) {
            if (rr < rmax) {
                float2 p0 = unpack2(a0[rr]), p1 = unpack2(a1[rr]);
                *(float4*)(g_static + (size_t)(r0 + rr) * D + col) =
                    make_float4(p0.x, p0.y, p1.x, p1.y);
            }
        }
        __syncwarp();
    }
}

// ---------------------------------------------------------------------------
// g_A = X @ W1, g_Y = X @ W2; X = relu(g_static) (use_h=0) or g_h (use_h=1).
__global__ void __launch_bounds__(256) k_gemmAB(
    const float* __restrict__ W1, const float* __restrict__ W2, int n, int use_h)
{
    extern __shared__ float sm[];
    float* sW1   = sm;                // 64 KB
    float* sW2   = sm + D * D;        // 64 KB
    float* stage = sm + 2 * D * D;    // 32 KB

    for (int i = threadIdx.x; i < D * D; i += blockDim.x) {
        sW1[i] = W1[i];
        sW2[i] = W2[i];
    }
    __syncthreads();

    int warp = threadIdx.x >> 5;
    int lane = threadIdx.x & 31;
    int col  = lane * 4;
    float* st = stage + warp * (8 * D);
    const float* X = use_h ? g_h : g_static;

    for (int r0 = blockIdx.x * 64 + warp * 8; r0 < n; r0 += gridDim.x * 64) {
        int rmax = n - r0; if (rmax > 8) rmax = 8;
#pragma unroll
        for (int rr = 0; rr < 8; rr++) {
            if (rr < rmax) {
                float4 v = *(const float4*)(X + (size_t)(r0 + rr) * D + col);
                if (!use_h) {
                    v.x = fmaxf(v.x, 0.f); v.y = fmaxf(v.y, 0.f);
                    v.z = fmaxf(v.z, 0.f); v.w = fmaxf(v.w, 0.f);
                }
                *(float4*)(st + rr * D + col) = v;
            }
        }
        __syncwarp();

        unsigned long long a0[8], a1[8], y0[8], y1[8];
#pragma unroll
        for (int rr = 0; rr < 8; rr++) {
            a0[rr] = 0ull; a1[rr] = 0ull; y0[rr] = 0ull; y1[rr] = 0ull;
        }

        for (int k = 0; k < D; k++) {
            ulonglong2 w1 = *(const ulonglong2*)(sW1 + k * D + col);
            ulonglong2 w2 = *(const ulonglong2*)(sW2 + k * D + col);
#pragma unroll
            for (int rr = 0; rr < 8; rr++) {
                unsigned long long xx = pack2(st[rr * D + k]);
                a0[rr] = ffma2(xx, w1.x, a0[rr]);
                a1[rr] = ffma2(xx, w1.y, a1[rr]);
                y0[rr] = ffma2(xx, w2.x, y0[rr]);
                y1[rr] = ffma2(xx, w2.y, y1[rr]);
            }
        }
#pragma unroll
        for (int rr = 0; rr < 8; rr++) {
            if (rr < rmax) {
                float2 pa0 = unpack2(a0[rr]), pa1 = unpack2(a1[rr]);
                float2 py0 = unpack2(y0[rr]), py1 = unpack2(y1[rr]);
                *(float4*)(g_A + (size_t)(r0 + rr) * D + col) =
                    make_float4(pa0.x, pa0.y, pa1.x, pa1.y);
                *(float4*)(g_Y + (size_t)(r0 + rr) * D + col) =
                    make_float4(py0.x, py0.y, py1.x, py1.y);
            }
        }
        __syncwarp();
    }
}

// ---------------------------------------------------------------------------
// Fused n2n spmm + merge: out[d] = relu(static[d] + A[d] + sum_{src in N(d)} Y[src])
// NOTE: device-global destination selected INSIDE device code (nullptr sentinel);
// passing g_h from host was the R2/R3 bug.
__global__ void __launch_bounds__(256) k_spmm_merge(float* __restrict__ out, int n)
{
    int lane = threadIdx.x & 31;
    int gw   = (blockIdx.x * blockDim.x + threadIdx.x) >> 5;
    int nw   = (gridDim.x * blockDim.x) >> 5;
    float* dst = out ? out : g_h;

    for (int d = gw; d < n; d += nw) {
        int j0 = g_off[1][d], j1 = g_off[1][d + 1];
        float4 s = ((const float4*)(g_static + (size_t)d * D))[lane];
        float4 a = ((const float4*)(g_A + (size_t)d * D))[lane];
        float4 acc  = make_float4(s.x + a.x, s.y + a.y, s.z + a.z, s.w + a.w);
        float4 acc2 = make_float4(0.f, 0.f, 0.f, 0.f);

        int j = j0;
        for (; j + 2 <= j1; j += 2) {
            int s0 = g_permB[j], s1 = g_permB[j + 1];
            float4 v0 = ((const float4*)(g_Y + (size_t)s0 * D))[lane];
            float4 v1 = ((const float4*)(g_Y + (size_t)s1 * D))[lane];
            acc.x += v0.x; acc.y += v0.y; acc.z += v0.z; acc.w += v0.w;
            acc2.x += v1.x; acc2.y += v1.y; acc2.z += v1.z; acc2.w += v1.w;
        }
        if (j < j1) {
            int s0 = g_permB[j];
            float4 v0 = ((const float4*)(g_Y + (size_t)s0 * D))[lane];
            acc.x += v0.x; acc.y += v0.y; acc.z += v0.z; acc.w += v0.w;
        }
        float4 o;
        o.x = fmaxf(acc.x + acc2.x, 0.f);
        o.y = fmaxf(acc.y + acc2.y, 0.f);
        o.z = fmaxf(acc.z + acc2.z, 0.f);
        o.w = fmaxf(acc.w + acc2.w, 0.f);
        ((float4*)(dst + (size_t)d * D))[lane] = o;
    }
}

// ---------------------------------------------------------------------------
extern "C" void kernel_launch(void* const* d_in, const int* in_sizes, int n_in,
                              void* d_out, int out_size)
{
    const float* edge_feat = (const float*)d_in[0];
    const float* W_e2l     = (const float*)d_in[1];
    const float* W0        = (const float*)d_in[2];
    const float* W1s[3] = { (const float*)d_in[3], (const float*)d_in[5], (const float*)d_in[7] };
    const float* W2s[3] = { (const float*)d_in[4], (const float*)d_in[6], (const float*)d_in[8] };
    const int* e2n_dst  = (const int*)d_in[9];
    const int* edge_src = (const int*)d_in[10];
    const int* edge_dst = (const int*)d_in[11];

    int E = in_sizes[9];
    int n = out_size / D;
    int nchunk = (n + 255) / 256;

    const int smem_w0 = (D * D + 8 * 8 * D) * (int)sizeof(float);        // 96 KB
    const int smem_ab = (2 * D * D + 8 * 8 * D) * (int)sizeof(float);    // 160 KB
    cudaFuncSetAttribute(k_gemm_w0, cudaFuncAttributeMaxDynamicSharedMemorySize, smem_w0);
    cudaFuncSetAttribute(k_gemmAB,  cudaFuncAttributeMaxDynamicSharedMemorySize, smem_ab);

    int gemm_blocks = (n + 63) / 64;
    int node_blocks = (n + 7) / 8;     // warp per node

    // --- CSR build (e2n: perm=edge id; n2n: perm=edge_src) ---
    k_zero_cnt<<<196, 256>>>(n);
    k_hist<<<1024, 256>>>(e2n_dst, edge_dst, E);
    dim3 sg(nchunk, 2);
    k_scan1<<<sg, 256>>>(n);
    k_scan2<<<1, 256>>>(n, nchunk);
    k_scan3<<<sg, 256>>>(n);
    k_fill<<<1024, 256>>>(e2n_dst, edge_dst, edge_src, E);

    // --- node pipeline ---
    k_edge_pool<<<node_blocks, 256>>>(edge_feat, W_e2l, n);
    k_gemm_w0<<<gemm_blocks, 256, smem_w0>>>(W0, n);

    for (int it = 0; it < 3; it++) {
        k_gemmAB<<<gemm_blocks, 256, smem_ab>>>(W1s[it], W2s[it], n, it > 0 ? 1 : 0);
        k_spmm_merge<<<node_blocks, 256>>>(it == 2 ? (float*)d_out : nullptr, n);
    }
}

// round 5
// speedup vs baseline: 1.5485x; 1.2223x over previous
#include <cuda_runtime.h>

#define D      128
#define EF     16
#define NMAX   50000
#define EMAX   1600000
#define NCHUNK_MAX 256   // ceil(NMAX/256) = 196 <= 256

// ---------------- scratch (device globals; zero-init, no allocation) -------
__device__ float g_pool[NMAX * D];     // e2n pooled edge messages
__device__ float g_static[NMAX * D];   // e2n_pool @ W0 (pre-relu)
__device__ float g_A[NMAX * D];        // static + X @ W1
__device__ float g_Y[NMAX * D];        // X @ W2
__device__ float g_h[NMAX * D];        // hidden state

__device__ int g_cnt[2][NMAX];         // [0]=e2n_dst hist, [1]=edge_dst hist
__device__ int g_off[2][NMAX + 1];
__device__ int g_cur[2][NMAX];
__device__ int g_csum[2][NCHUNK_MAX];
__device__ int g_coff[2][NCHUNK_MAX];
__device__ int g_permA[EMAX];          // edge ids grouped by e2n_dst
__device__ int g_permB[EMAX];          // edge_src values grouped by edge_dst

// ---------------- f32x2 packed math helpers --------------------------------
__device__ __forceinline__ unsigned long long pack2(float x) {
    unsigned int u = __float_as_uint(x);
    unsigned long long r;
    asm("mov.b64 %0, {%1, %2};" : "=l"(r) : "r"(u), "r"(u));
    return r;
}
__device__ __forceinline__ unsigned long long ffma2(
    unsigned long long a, unsigned long long b, unsigned long long c) {
    unsigned long long d;
    asm("fma.rn.f32x2 %0, %1, %2, %3;" : "=l"(d) : "l"(a), "l"(b), "l"(c));
    return d;
}
__device__ __forceinline__ float2 unpack2(unsigned long long v) {
    unsigned int lo, hi;
    asm("mov.b64 {%0, %1}, %2;" : "=r"(lo), "=r"(hi) : "l"(v));
    return make_float2(__uint_as_float(lo), __uint_as_float(hi));
}

// ---------------- CSR builders ---------------------------------------------
__global__ void k_zero_cnt(int n) {
    int i = blockIdx.x * blockDim.x + threadIdx.x;
    int s = gridDim.x * blockDim.x;
    for (; i < n; i += s) { g_cnt[0][i] = 0; g_cnt[1][i] = 0; }
}

__global__ void k_hist(const int* __restrict__ e2n, const int* __restrict__ ndst, int E) {
    int i = blockIdx.x * blockDim.x + threadIdx.x;
    int s = gridDim.x * blockDim.x;
    for (; i < E; i += s) {
        atomicAdd(&g_cnt[0][e2n[i]], 1);
        atomicAdd(&g_cnt[1][ndst[i]], 1);
    }
}

__global__ void k_scan1(int n) {
    __shared__ int sh[256];
    int a = blockIdx.y;
    int i = blockIdx.x * 256 + threadIdx.x;
    sh[threadIdx.x] = (i < n) ? g_cnt[a][i] : 0;
    __syncthreads();
    for (int o = 128; o > 0; o >>= 1) {
        if (threadIdx.x < o) sh[threadIdx.x] += sh[threadIdx.x + o];
        __syncthreads();
    }
    if (threadIdx.x == 0) g_csum[a][blockIdx.x] = sh[0];
}

__global__ void k_scan2(int n, int nchunk) {
    __shared__ int sh[256];
    for (int a = 0; a < 2; a++) {
        int v = (threadIdx.x < nchunk) ? g_csum[a][threadIdx.x] : 0;
        sh[threadIdx.x] = v;
        __syncthreads();
        for (int o = 1; o < 256; o <<= 1) {
            int t = (threadIdx.x >= o) ? sh[threadIdx.x - o] : 0;
            __syncthreads();
            sh[threadIdx.x] += t;
            __syncthreads();
        }
        if (threadIdx.x < nchunk) g_coff[a][threadIdx.x] = sh[threadIdx.x] - v;
        if (threadIdx.x == 255)   g_off[a][n] = sh[255];
        __syncthreads();
    }
}

__global__ void k_scan3(int n) {
    __shared__ int sh[256];
    int a = blockIdx.y;
    int i = blockIdx.x * 256 + threadIdx.x;
    int v = (i < n) ? g_cnt[a][i] : 0;
    sh[threadIdx.x] = v;
    __syncthreads();
    for (int o = 1; o < 256; o <<= 1) {
        int t = (threadIdx.x >= o) ? sh[threadIdx.x - o] : 0;
        __syncthreads();
        sh[threadIdx.x] += t;
        __syncthreads();
    }
    if (i < n) {
        int excl = g_coff[a][blockIdx.x] + sh[threadIdx.x] - v;
        g_off[a][i] = excl;
        g_cur[a][i] = excl;
    }
}

__global__ void k_fill(const int* __restrict__ e2n, const int* __restrict__ ndst,
                       const int* __restrict__ nsrc, int E) {
    int i = blockIdx.x * blockDim.x + threadIdx.x;
    int s = gridDim.x * blockDim.x;
    for (; i < E; i += s) {
        int pa = atomicAdd(&g_cur[0][e2n[i]], 1);
        g_permA[pa] = i;
        int pb = atomicAdd(&g_cur[1][ndst[i]], 1);
        g_permB[pb] = nsrc[i];
    }
}

// ---------------------------------------------------------------------------
// Per-node e2n pool. Weights held in REGISTERS (32 ull = 64 regs/lane).
// Edge loop unrolled x2 for load/shfl ILP.
__global__ void __launch_bounds__(256) k_edge_pool(
    const float* __restrict__ ef, const float* __restrict__ We, int n)
{
    int lane = threadIdx.x & 31;
    int col  = lane * 4;

    ulonglong2 w[EF];
#pragma unroll
    for (int k = 0; k < EF; k++)
        w[k] = *(const ulonglong2*)(We + k * D + col);

    int gw = (blockIdx.x * blockDim.x + threadIdx.x) >> 5;
    int nw = (gridDim.x * blockDim.x) >> 5;

    for (int d = gw; d < n; d += nw) {
        int j0 = g_off[0][d], j1 = g_off[0][d + 1];
        float a0 = 0.f, a1 = 0.f, a2 = 0.f, a3 = 0.f;

        int j = j0;
        for (; j + 2 <= j1; j += 2) {
            int e0 = g_permA[j], e1 = g_permA[j + 1];
            float f0 = (lane < EF) ? ef[(size_t)e0 * EF + lane] : 0.f;
            float f1 = (lane < EF) ? ef[(size_t)e1 * EF + lane] : 0.f;
            unsigned long long t00 = 0ull, t01 = 0ull, t10 = 0ull, t11 = 0ull;
#pragma unroll
            for (int k = 0; k < EF; k++) {
                unsigned long long x0 = pack2(__shfl_sync(0xffffffffu, f0, k));
                unsigned long long x1 = pack2(__shfl_sync(0xffffffffu, f1, k));
                t00 = ffma2(x0, w[k].x, t00);
                t01 = ffma2(x0, w[k].y, t01);
                t10 = ffma2(x1, w[k].x, t10);
                t11 = ffma2(x1, w[k].y, t11);
            }
            float2 p00 = unpack2(t00), p01 = unpack2(t01);
            float2 p10 = unpack2(t10), p11 = unpack2(t11);
            a0 += fmaxf(p00.x, 0.f) + fmaxf(p10.x, 0.f);
            a1 += fmaxf(p00.y, 0.f) + fmaxf(p10.y, 0.f);
            a2 += fmaxf(p01.x, 0.f) + fmaxf(p11.x, 0.f);
            a3 += fmaxf(p01.y, 0.f) + fmaxf(p11.y, 0.f);
        }
        if (j < j1) {
            int e0 = g_permA[j];
            float f0 = (lane < EF) ? ef[(size_t)e0 * EF + lane] : 0.f;
            unsigned long long t00 = 0ull, t01 = 0ull;
#pragma unroll
            for (int k = 0; k < EF; k++) {
                unsigned long long x0 = pack2(__shfl_sync(0xffffffffu, f0, k));
                t00 = ffma2(x0, w[k].x, t00);
                t01 = ffma2(x0, w[k].y, t01);
            }
            float2 p00 = unpack2(t00), p01 = unpack2(t01);
            a0 += fmaxf(p00.x, 0.f);
            a1 += fmaxf(p00.y, 0.f);
            a2 += fmaxf(p01.x, 0.f);
            a3 += fmaxf(p01.y, 0.f);
        }
        *(float4*)(g_pool + (size_t)d * D + col) = make_float4(a0, a1, a2, a3);
    }
}

// ---------------------------------------------------------------------------
// static = pool @ W0 ; h = relu(static).  Persistent grid, weights loaded once.
__global__ void __launch_bounds__(256) k_gemm_w0(const float* __restrict__ W, int n)
{
    extern __shared__ float sm[];
    float* sW    = sm;            // D*D (64 KB)
    float* stage = sm + D * D;    // 8*8*D (32 KB)

    for (int i = threadIdx.x; i < D * D; i += blockDim.x) sW[i] = W[i];
    __syncthreads();

    int warp = threadIdx.x >> 5;
    int lane = threadIdx.x & 31;
    int col  = lane * 4;
    float* st = stage + warp * (8 * D);

    for (int r0 = blockIdx.x * 64 + warp * 8; r0 < n; r0 += gridDim.x * 64) {
        int rmax = n - r0; if (rmax > 8) rmax = 8;
#pragma unroll
        for (int rr = 0; rr < 8; rr++)
            if (rr < rmax)
                *(float4*)(st + rr * D + col) =
                    *(const float4*)(g_pool + (size_t)(r0 + rr) * D + col);
        __syncwarp();

        unsigned long long a0[8], a1[8];
#pragma unroll
        for (int rr = 0; rr < 8; rr++) { a0[rr] = 0ull; a1[rr] = 0ull; }

        for (int k = 0; k < D; k++) {
            ulonglong2 w = *(const ulonglong2*)(sW + k * D + col);
#pragma unroll
            for (int rr = 0; rr < 8; rr++) {
                unsigned long long xx = pack2(st[rr * D + k]);
                a0[rr] = ffma2(xx, w.x, a0[rr]);
                a1[rr] = ffma2(xx, w.y, a1[rr]);
            }
        }
#pragma unroll
        for (int rr = 0; rr < 8; rr++) {
            if (rr < rmax) {
                float2 p0 = unpack2(a0[rr]), p1 = unpack2(a1[rr]);
                float4 s = make_float4(p0.x, p0.y, p1.x, p1.y);
                *(float4*)(g_static + (size_t)(r0 + rr) * D + col) = s;
                *(float4*)(g_h + (size_t)(r0 + rr) * D + col) =
                    make_float4(fmaxf(s.x, 0.f), fmaxf(s.y, 0.f),
                                fmaxf(s.z, 0.f), fmaxf(s.w, 0.f));
            }
        }
        __syncwarp();
    }
}

// ---------------------------------------------------------------------------
// g_A = static + h @ W1 ; g_Y = h @ W2.  Persistent grid.
__global__ void __launch_bounds__(256) k_gemmAB(
    const float* __restrict__ W1, const float* __restrict__ W2, int n)
{
    extern __shared__ float sm[];
    float* sW1   = sm;                // 64 KB
    float* sW2   = sm + D * D;        // 64 KB
    float* stage = sm + 2 * D * D;    // 32 KB

    for (int i = threadIdx.x; i < D * D; i += blockDim.x) {
        sW1[i] = W1[i];
        sW2[i] = W2[i];
    }
    __syncthreads();

    int warp = threadIdx.x >> 5;
    int lane = threadIdx.x & 31;
    int col  = lane * 4;
    float* st = stage + warp * (8 * D);

    for (int r0 = blockIdx.x * 64 + warp * 8; r0 < n; r0 += gridDim.x * 64) {
        int rmax = n - r0; if (rmax > 8) rmax = 8;
#pragma unroll
        for (int rr = 0; rr < 8; rr++)
            if (rr < rmax)
                *(float4*)(st + rr * D + col) =
                    *(const float4*)(g_h + (size_t)(r0 + rr) * D + col);
        __syncwarp();

        unsigned long long a0[8], a1[8], y0[8], y1[8];
#pragma unroll
        for (int rr = 0; rr < 8; rr++) {
            a0[rr] = 0ull; a1[rr] = 0ull; y0[rr] = 0ull; y1[rr] = 0ull;
        }

        for (int k = 0; k < D; k++) {
            ulonglong2 w1 = *(const ulonglong2*)(sW1 + k * D + col);
            ulonglong2 w2 = *(const ulonglong2*)(sW2 + k * D + col);
#pragma unroll
            for (int rr = 0; rr < 8; rr++) {
                unsigned long long xx = pack2(st[rr * D + k]);
                a0[rr] = ffma2(xx, w1.x, a0[rr]);
                a1[rr] = ffma2(xx, w1.y, a1[rr]);
                y0[rr] = ffma2(xx, w2.x, y0[rr]);
                y1[rr] = ffma2(xx, w2.y, y1[rr]);
            }
        }
#pragma unroll
        for (int rr = 0; rr < 8; rr++) {
            if (rr < rmax) {
                float4 s = *(const float4*)(g_static + (size_t)(r0 + rr) * D + col);
                float2 pa0 = unpack2(a0[rr]), pa1 = unpack2(a1[rr]);
                float2 py0 = unpack2(y0[rr]), py1 = unpack2(y1[rr]);
                *(float4*)(g_A + (size_t)(r0 + rr) * D + col) =
                    make_float4(s.x + pa0.x, s.y + pa0.y, s.z + pa1.x, s.w + pa1.y);
                *(float4*)(g_Y + (size_t)(r0 + rr) * D + col) =
                    make_float4(py0.x, py0.y, py1.x, py1.y);
            }
        }
        __syncwarp();
    }
}

// ---------------------------------------------------------------------------
// Fused n2n spmm + merge: out[d] = relu(A[d] + sum_{src in N(d)} Y[src])
// (A already contains static + h@W1.)  Unroll x4 with index prefetch.
__global__ void __launch_bounds__(256) k_spmm_merge(float* __restrict__ out, int n)
{
    int lane = threadIdx.x & 31;
    int gw   = (blockIdx.x * blockDim.x + threadIdx.x) >> 5;
    int nw   = (gridDim.x * blockDim.x) >> 5;
    float* dst = out ? out : g_h;   // device-side select (host g_h addr is invalid)

    for (int d = gw; d < n; d += nw) {
        int j0 = g_off[1][d], j1 = g_off[1][d + 1];
        float4 acc0 = ((const float4*)(g_A + (size_t)d * D))[lane];
        float4 acc1 = make_float4(0.f, 0.f, 0.f, 0.f);
        float4 acc2 = make_float4(0.f, 0.f, 0.f, 0.f);
        float4 acc3 = make_float4(0.f, 0.f, 0.f, 0.f);

        int j = j0;
        for (; j + 4 <= j1; j += 4) {
            int s0 = g_permB[j],     s1 = g_permB[j + 1];
            int s2 = g_permB[j + 2], s3 = g_permB[j + 3];
            float4 v0 = ((const float4*)(g_Y + (size_t)s0 * D))[lane];
            float4 v1 = ((const float4*)(g_Y + (size_t)s1 * D))[lane];
            float4 v2 = ((const float4*)(g_Y + (size_t)s2 * D))[lane];
            float4 v3 = ((const float4*)(g_Y + (size_t)s3 * D))[lane];
            acc0.x += v0.x; acc0.y += v0.y; acc0.z += v0.z; acc0.w += v0.w;
            acc1.x += v1.x; acc1.y += v1.y; acc1.z += v1.z; acc1.w += v1.w;
            acc2.x += v2.x; acc2.y += v2.y; acc2.z += v2.z; acc2.w += v2.w;
            acc3.x += v3.x; acc3.y += v3.y; acc3.z += v3.z; acc3.w += v3.w;
        }
        for (; j < j1; j++) {
            int s0 = g_permB[j];
            float4 v0 = ((const float4*)(g_Y + (size_t)s0 * D))[lane];
            acc0.x += v0.x; acc0.y += v0.y; acc0.z += v0.z; acc0.w += v0.w;
        }
        float4 o;
        o.x = fmaxf(acc0.x + acc1.x + acc2.x + acc3.x, 0.f);
        o.y = fmaxf(acc0.y + acc1.y + acc2.y + acc3.y, 0.f);
        o.z = fmaxf(acc0.z + acc1.z + acc2.z + acc3.z, 0.f);
        o.w = fmaxf(acc0.w + acc1.w + acc2.w + acc3.w, 0.f);
        ((float4*)(dst + (size_t)d * D))[lane] = o;
    }
}

// ---------------------------------------------------------------------------
extern "C" void kernel_launch(void* const* d_in, const int* in_sizes, int n_in,
                              void* d_out, int out_size)
{
    const float* edge_feat = (const float*)d_in[0];
    const float* W_e2l     = (const float*)d_in[1];
    const float* W0        = (const float*)d_in[2];
    const float* W1s[3] = { (const float*)d_in[3], (const float*)d_in[5], (const float*)d_in[7] };
    const float* W2s[3] = { (const float*)d_in[4], (const float*)d_in[6], (const float*)d_in[8] };
    const int* e2n_dst  = (const int*)d_in[9];
    const int* edge_src = (const int*)d_in[10];
    const int* edge_dst = (const int*)d_in[11];

    int E = in_sizes[9];
    int n = out_size / D;
    int nchunk = (n + 255) / 256;

    const int smem_w0 = (D * D + 8 * 8 * D) * (int)sizeof(float);        // 96 KB
    const int smem_ab = (2 * D * D + 8 * 8 * D) * (int)sizeof(float);    // 160 KB
    cudaFuncSetAttribute(k_gemm_w0, cudaFuncAttributeMaxDynamicSharedMemorySize, smem_w0);
    cudaFuncSetAttribute(k_gemmAB,  cudaFuncAttributeMaxDynamicSharedMemorySize, smem_ab);

    int node_blocks = (n + 7) / 8;     // warp per node

    // --- CSR build (e2n: perm=edge id; n2n: perm=edge_src) ---
    k_zero_cnt<<<196, 256>>>(n);
    k_hist<<<1024, 256>>>(e2n_dst, edge_dst, E);
    dim3 sg(nchunk, 2);
    k_scan1<<<sg, 256>>>(n);
    k_scan2<<<1, 256>>>(n, nchunk);
    k_scan3<<<sg, 256>>>(n);
    k_fill<<<1024, 256>>>(e2n_dst, edge_dst, edge_src, E);

    // --- node pipeline (persistent GEMM grids: weights loaded once per SM) ---
    k_edge_pool<<<node_blocks, 256>>>(edge_feat, W_e2l, n);
    k_gemm_w0<<<296, 256, smem_w0>>>(W0, n);

    for (int it = 0; it < 3; it++) {
        k_gemmAB<<<148, 256, smem_ab>>>(W1s[it], W2s[it], n);
        k_spmm_merge<<<node_blocks, 256>>>(it == 2 ? (float*)d_out : nullptr, n);
    }
}